// round 16
// baseline (speedup 1.0000x reference)
#include <cuda_runtime.h>
#include <cuda_fp16.h>
#include <cuda_bf16.h>

namespace {
constexpr int kNUser = 50000;
constexpr int kN     = 80000;      // total nodes
constexpr int kE     = 1000000;    // 2 * NNZ symmetric edges
constexpr int kD     = 64;
constexpr int kChunk = 1024;
constexpr int kNChunk = (kN + kChunk - 1) / kChunk;   // 79
}

// ---------------- device scratch (static, no allocation) ----------------
__device__ float    g_A[kE * 4];        // routing logits, CSR-slot order
__device__ float    g_normA[kE * 4];    // softmax(A), CSR-slot order
__device__ float    g_buf0[kN * kD];    // initial ego (layer-0 input; never overwritten)
__device__ float    g_buf1[kN * kD];    // layer-0 output = layer-1 input
__device__ unsigned g_egoS0[kN * 32];   // prescaled ego, fp16 x2, ping (128B/node)
__device__ unsigned g_egoS1[kN * 32];   // pong
__device__ unsigned g_Tn8_0[kN * 16];   // tanh chunks, int8 per-factor max-scaled, ping (64B/node)
__device__ unsigned g_Tn8_1[kN * 16];   // pong
__device__ unsigned short g_Tsc0[kN * 4]; // per-(node,factor) Tn dequant scale, fp16, ping
__device__ unsigned short g_Tsc1[kN * 4]; // pong
__device__ float    g_dinvA[kN * 4];    // 1/sqrt(degree-weight), ping
__device__ float    g_dinvB[kN * 4];    // pong
__device__ int      g_ptr[kN + 1];      // CSR row pointers (by head)
__device__ int      g_cnt[kN];          // histogram / fill counters
__device__ int      g_csr_t[kE];        // tail node per CSR slot
__device__ int      g_bsum[kNChunk];    // per-chunk sums for multi-block scan
__device__ int      g_red_done;         // last-block-done counter (self-resetting)

__device__ __forceinline__ unsigned pack_h2(float a, float b) {
    __half2 h = __floats2half2_rn(a, b);
    return *reinterpret_cast<unsigned*>(&h);
}
__device__ __forceinline__ unsigned pack_b4(int a, int b, int c, int d) {
    return (unsigned)(a & 0xFF) | ((unsigned)(b & 0xFF) << 8) |
           ((unsigned)(c & 0xFF) << 16) | ((unsigned)(d & 0xFF) << 24);
}
__device__ __forceinline__ unsigned short h_bits(float x) {
    __half h = __float2half(x);
    return *reinterpret_cast<unsigned short*>(&h);
}
__device__ __forceinline__ float h_val(unsigned short b) {
    __half h = *reinterpret_cast<__half*>(&b);
    return __half2float(h);
}

// ---------------- init (+ cnt zeroing folded in) ----------------
__global__ void k_init_ego(const float* __restrict__ user, const float* __restrict__ item) {
    int i = blockIdx.x * blockDim.x + threadIdx.x;
    if (i >= kN * kD) return;
    g_buf0[i] = (i < kNUser * kD) ? user[i] : item[i - kNUser * kD];
    if (i < kN) g_cnt[i] = 0;
}

// ---------------- CSR build ----------------
__global__ void k_count(const int* __restrict__ h) {
    int e = blockIdx.x * blockDim.x + threadIdx.x;
    if (e >= kE) return;
    atomicAdd(&g_cnt[h[e]], 1);
}

// chunk reduce + (last block) scan of the 79 block sums
__global__ void k_chunk_reduce() {            // kNChunk blocks x 256
    __shared__ int wsum[8];
    __shared__ int lastFlag;
    const int lane = threadIdx.x & 31, wrp = threadIdx.x >> 5;
    int base = blockIdx.x * kChunk + (int)threadIdx.x * 4;
    int s = 0;
    #pragma unroll
    for (int k = 0; k < 4; k++) { int i = base + k; if (i < kN) s += g_cnt[i]; }
    #pragma unroll
    for (int o = 16; o >= 1; o >>= 1) s += __shfl_xor_sync(0xffffffffu, s, o);
    if (lane == 0) wsum[wrp] = s;
    __syncthreads();
    if (threadIdx.x == 0) {
        int t = 0;
        #pragma unroll
        for (int k = 0; k < 8; k++) t += wsum[k];
        g_bsum[blockIdx.x] = t;
        __threadfence();
        int v = atomicAdd(&g_red_done, 1);
        lastFlag = (v == (int)gridDim.x - 1) ? 1 : 0;
    }
    __syncthreads();
    if (lastFlag && threadIdx.x < 32) {
        int carry = 0;
        for (int b2 = 0; b2 < kNChunk; b2 += 32) {
            int i = b2 + (int)threadIdx.x;
            int v = (i < kNChunk) ? __ldcg(&g_bsum[i]) : 0;
            int x = v;
            #pragma unroll
            for (int o = 1; o < 32; o <<= 1) {
                int y = __shfl_up_sync(0xffffffffu, x, o);
                if ((int)threadIdx.x >= o) x += y;
            }
            if (i < kNChunk) g_bsum[i] = carry + x - v;   // exclusive
            carry += __shfl_sync(0xffffffffu, x, 31);
        }
        if (threadIdx.x == 0) { g_ptr[kN] = carry; g_red_done = 0; }
    }
}

// chunk scan + dinv0 folded in (degree is in registers here)
__global__ void k_chunk_scan() {              // kNChunk blocks x 256
    __shared__ int wsum[8];
    const int lane = threadIdx.x & 31, wrp = threadIdx.x >> 5;
    int base = blockIdx.x * kChunk + (int)threadIdx.x * 4;
    int v0 = 0, v1 = 0, v2 = 0, v3 = 0;
    if (base + 3 < kN) {
        int4 v = *reinterpret_cast<const int4*>(&g_cnt[base]);
        v0 = v.x; v1 = v.y; v2 = v.z; v3 = v.w;
    } else {
        if (base + 0 < kN) v0 = g_cnt[base + 0];
        if (base + 1 < kN) v1 = g_cnt[base + 1];
        if (base + 2 < kN) v2 = g_cnt[base + 2];
        if (base + 3 < kN) v3 = g_cnt[base + 3];
    }
    int tot = v0 + v1 + v2 + v3;
    int x = tot;
    #pragma unroll
    for (int o = 1; o < 32; o <<= 1) {
        int y = __shfl_up_sync(0xffffffffu, x, o);
        if (lane >= o) x += y;
    }
    if (lane == 31) wsum[wrp] = x;
    __syncthreads();
    if (wrp == 0 && lane < 8) {
        int s = wsum[lane], xs = s;
        #pragma unroll
        for (int o = 1; o < 8; o <<= 1) {
            int y = __shfl_up_sync(0xffu, xs, o);
            if (lane >= o) xs += y;
        }
        wsum[lane] = xs - s;
    }
    __syncthreads();
    int ex = g_bsum[blockIdx.x] + wsum[wrp] + (x - tot);
    int vv[4] = {v0, v1, v2, v3};
    int pre[4] = {0, v0, v0 + v1, v0 + v1 + v2};
    #pragma unroll
    for (int k = 0; k < 4; k++) {
        int n = base + k;
        if (n < kN) {
            g_ptr[n] = ex + pre[k];
            g_cnt[n] = 0;
            float di = rsqrtf(fmaxf(0.25f * (float)vv[k], 1e-8f));
            reinterpret_cast<float4*>(g_dinvA)[n] = make_float4(di, di, di, di);
        }
    }
}

// fill CSR + A/normA init + layer-0 tail prep (Tn8_0 max-scaled, Tsc0, egoS0)
__global__ void k_fill_tail(const int* __restrict__ h, const int* __restrict__ t) {
    int i = blockIdx.x * blockDim.x + threadIdx.x;
    if (i < kE) {
        int hn   = h[i];
        int slot = g_ptr[hn] + atomicAdd(&g_cnt[hn], 1);
        g_csr_t[slot] = t[i];
        reinterpret_cast<float4*>(g_A)[slot]     = make_float4(1.f, 1.f, 1.f, 1.f);
        reinterpret_cast<float4*>(g_normA)[slot] = make_float4(.25f, .25f, .25f, .25f);
    }
    if (i < kN * 4) {        // one (node,factor) per thread: 16 dims
        const float4* src = reinterpret_cast<const float4*>(g_buf0) + i * 4;
        float4 v0 = src[0], v1 = src[1], v2 = src[2], v3 = src[3];
        float ss = v0.x*v0.x + v0.y*v0.y + v0.z*v0.z + v0.w*v0.w
                 + v1.x*v1.x + v1.y*v1.y + v1.z*v1.z + v1.w*v1.w
                 + v2.x*v2.x + v2.y*v2.y + v2.z*v2.z + v2.w*v2.w
                 + v3.x*v3.x + v3.y*v3.y + v3.z*v3.z + v3.w*v3.w;
        float inv = 1.0f / fmaxf(sqrtf(ss), 1e-12f);
        float tv[16];
        tv[0]=tanhf(v0.x*inv); tv[1]=tanhf(v0.y*inv); tv[2]=tanhf(v0.z*inv); tv[3]=tanhf(v0.w*inv);
        tv[4]=tanhf(v1.x*inv); tv[5]=tanhf(v1.y*inv); tv[6]=tanhf(v1.z*inv); tv[7]=tanhf(v1.w*inv);
        tv[8]=tanhf(v2.x*inv); tv[9]=tanhf(v2.y*inv); tv[10]=tanhf(v2.z*inv); tv[11]=tanhf(v2.w*inv);
        tv[12]=tanhf(v3.x*inv); tv[13]=tanhf(v3.y*inv); tv[14]=tanhf(v3.z*inv); tv[15]=tanhf(v3.w*inv);
        float m = 1e-12f;
        #pragma unroll
        for (int k = 0; k < 16; k++) m = fmaxf(m, fabsf(tv[k]));
        float qs = 127.0f / m;
        uint4 tq;
        tq.x = pack_b4(__float2int_rn(tv[0]*qs),  __float2int_rn(tv[1]*qs),
                       __float2int_rn(tv[2]*qs),  __float2int_rn(tv[3]*qs));
        tq.y = pack_b4(__float2int_rn(tv[4]*qs),  __float2int_rn(tv[5]*qs),
                       __float2int_rn(tv[6]*qs),  __float2int_rn(tv[7]*qs));
        tq.z = pack_b4(__float2int_rn(tv[8]*qs),  __float2int_rn(tv[9]*qs),
                       __float2int_rn(tv[10]*qs), __float2int_rn(tv[11]*qs));
        tq.w = pack_b4(__float2int_rn(tv[12]*qs), __float2int_rn(tv[13]*qs),
                       __float2int_rn(tv[14]*qs), __float2int_rn(tv[15]*qs));
        reinterpret_cast<uint4*>(g_Tn8_0)[i] = tq;
        g_Tsc0[i] = h_bits(m * (1.0f / 127.0f));
        float di = g_dinvA[i];
        uint4 s0, s1;
        s0.x = pack_h2(v0.x*di, v0.y*di);
        s0.y = pack_h2(v0.z*di, v0.w*di);
        s0.z = pack_h2(v1.x*di, v1.y*di);
        s0.w = pack_h2(v1.z*di, v1.w*di);
        s1.x = pack_h2(v2.x*di, v2.y*di);
        s1.y = pack_h2(v2.z*di, v2.w*di);
        s1.z = pack_h2(v3.x*di, v3.y*di);
        s1.w = pack_h2(v3.z*di, v3.w*di);
        reinterpret_cast<uint4*>(g_egoS0)[i * 2]     = s0;
        reinterpret_cast<uint4*>(g_egoS0)[i * 2 + 1] = s1;
    }
}

// ---------------- fused iteration ----------------
// one warp per node. MP: fp16 egoS row (128B, 1 line/edge), smem-staged weights.
// Routing: lane-per-edge; Tn row = 64B int8 per-factor max-scaled + 8B fp16 scales;
// head int8 per-factor max-scaled in smem; dp4a dot, per-lane softmax.
// mode: 0 = routing, egoS_next = ego[w]*dinvN
//       1 = routing + fe write, egoS_next = acc*dinvN, Tn8/Tsc_next from acc
//       2 = final output
__global__ void __launch_bounds__(256) k_fused(
        int sel_in, int dsel, int esel, int tsel, int mode, float* __restrict__ out)
{
    __shared__ int            sm_t[8][32];
    __shared__ float          sm_wT[8][4][33];
    __shared__ unsigned short sm_hq[8][32];   // int8x2 quantized head
    __shared__ float          sm_hs[8][4];    // per-factor head dequant scales

    const int warp = threadIdx.x >> 5;
    const int lane = threadIdx.x & 31;
    const int w = blockIdx.x * 8 + warp;
    const int f = lane >> 3;

    const float*          ego    = sel_in ? g_buf1 : g_buf0;
    float*                fe     = sel_in ? g_buf0 : g_buf1;
    const unsigned*       egoSC  = esel ? g_egoS1 : g_egoS0;
    unsigned*             egoSN  = esel ? g_egoS0 : g_egoS1;
    const unsigned*       Tn8C   = tsel ? g_Tn8_1 : g_Tn8_0;
    unsigned*             Tn8N   = tsel ? g_Tn8_0 : g_Tn8_1;
    const unsigned short* TscC   = tsel ? g_Tsc1 : g_Tsc0;
    unsigned short*       TscN   = tsel ? g_Tsc0 : g_Tsc1;
    const float4*         dinvC  = reinterpret_cast<const float4*>(dsel ? g_dinvB : g_dinvA);
    float4*               dinvN  = reinterpret_cast<float4*>(dsel ? g_dinvA : g_dinvB);
    const float4*         normA  = reinterpret_cast<const float4*>(g_normA);
    float4*               normAo = reinterpret_cast<float4*>(g_normA);
    float4*               Ap     = reinterpret_cast<float4*>(g_A);

    const int s = g_ptr[w], e = g_ptr[w + 1];
    const bool single = (e - s) <= 32;     // sm_t holds ALL tails after MP

    // ---- message passing ----
    float2 acc = make_float2(0.f, 0.f);
    for (int base = s; base < e; base += 32) {
        int j = base + lane;
        bool valid = j < e;
        int t = valid ? g_csr_t[j] : 0;
        float4 na = valid ? normA[j] : make_float4(0.f, 0.f, 0.f, 0.f);
        sm_t[warp][lane] = t;
        sm_wT[warp][0][lane] = na.x;
        sm_wT[warp][1][lane] = na.y;
        sm_wT[warp][2][lane] = na.z;
        sm_wT[warp][3][lane] = na.w;
        __syncwarp();
        int cnt = min(32, e - base);
        #pragma unroll 8
        for (int k = 0; k < cnt; k++) {
            int   tk = sm_t[warp][k];
            float wk = sm_wT[warp][f][k];
            float2 ev = __half22float2(*reinterpret_cast<const __half2*>(&egoSC[tk * 32 + lane]));
            acc.x += wk * ev.x;
            acc.y += wk * ev.y;
        }
        __syncwarp();
    }
    {
        float4 dh = dinvC[w];
        float ds = (f == 0) ? dh.x : (f == 1) ? dh.y : (f == 2) ? dh.z : dh.w;
        acc.x *= ds; acc.y *= ds;
    }

    if (mode == 2) {
        float2 a = reinterpret_cast<const float2*>(g_buf0 + w * kD)[lane];
        float2 b = reinterpret_cast<const float2*>(ego + w * kD)[lane];
        float2 o;
        o.x = (a.x + b.x + acc.x) * (1.0f / 3.0f);
        o.y = (a.y + b.y + acc.y) * (1.0f / 3.0f);
        reinterpret_cast<float2*>(out + w * kD)[lane] = o;
        return;
    }

    if (mode == 1)
        reinterpret_cast<float2*>(fe + w * kD)[lane] = acc;

    // ---- head inverse norm + per-factor max-scaled int8 quantization ----
    float ss = acc.x * acc.x + acc.y * acc.y;
    #pragma unroll
    for (int o = 4; o >= 1; o >>= 1) ss += __shfl_xor_sync(0xffffffffu, ss, o);
    const float hinv = 1.0f / fmaxf(sqrtf(ss), 1e-12f);
    const float hx = acc.x * hinv, hy = acc.y * hinv;
    float hm = fmaxf(fabsf(hx), fabsf(hy));
    #pragma unroll
    for (int o = 4; o >= 1; o >>= 1) hm = fmaxf(hm, __shfl_xor_sync(0xffffffffu, hm, o));
    hm = fmaxf(hm, 1e-12f);
    {
        float qs = 127.0f / hm;
        int bx = __float2int_rn(hx * qs);
        int by = __float2int_rn(hy * qs);
        sm_hq[warp][lane] = (unsigned short)((bx & 0xFF) | ((by & 0xFF) << 8));
        if ((lane & 7) == 0) sm_hs[warp][f] = hm * (1.0f / 127.0f);
    }
    __syncwarp();
    const float Hs0 = sm_hs[warp][0], Hs1 = sm_hs[warp][1];
    const float Hs2 = sm_hs[warp][2], Hs3 = sm_hs[warp][3];

    // ---- routing: lane-per-edge, int8 Tn row (64B) + fp16 scales (8B), dp4a ----
    const int* hq32 = reinterpret_cast<const int*>(&sm_hq[warp][0]);  // 16 words
    float4 dval = make_float4(0.f, 0.f, 0.f, 0.f);
    for (int base = s; base < e; base += 32) {
        int j = base + lane;
        if (j < e) {
            int t = single ? sm_t[warp][lane] : g_csr_t[j];
            const uint4* tn = reinterpret_cast<const uint4*>(Tn8C) + t * 4;
            uint2 tsw = *reinterpret_cast<const uint2*>(&TscC[t * 4]);
            float2 ts01 = __half22float2(*reinterpret_cast<__half2*>(&tsw.x));
            float2 ts23 = __half22float2(*reinterpret_cast<__half2*>(&tsw.y));
            int d0, d1, d2, d3;
            {
                uint4 v = tn[0];   // factor 0, dims 0..15
                d0 = __dp4a((int)v.x, hq32[0], 0);
                d0 = __dp4a((int)v.y, hq32[1], d0);
                d0 = __dp4a((int)v.z, hq32[2], d0);
                d0 = __dp4a((int)v.w, hq32[3], d0);
            }
            {
                uint4 v = tn[1];   // factor 1
                d1 = __dp4a((int)v.x, hq32[4], 0);
                d1 = __dp4a((int)v.y, hq32[5], d1);
                d1 = __dp4a((int)v.z, hq32[6], d1);
                d1 = __dp4a((int)v.w, hq32[7], d1);
            }
            {
                uint4 v = tn[2];   // factor 2
                d2 = __dp4a((int)v.x, hq32[8],  0);
                d2 = __dp4a((int)v.y, hq32[9],  d2);
                d2 = __dp4a((int)v.z, hq32[10], d2);
                d2 = __dp4a((int)v.w, hq32[11], d2);
            }
            {
                uint4 v = tn[3];   // factor 3
                d3 = __dp4a((int)v.x, hq32[12], 0);
                d3 = __dp4a((int)v.y, hq32[13], d3);
                d3 = __dp4a((int)v.z, hq32[14], d3);
                d3 = __dp4a((int)v.w, hq32[15], d3);
            }
            float4 An = Ap[j];
            An.x += (float)d0 * ts01.x * Hs0;
            An.y += (float)d1 * ts01.y * Hs1;
            An.z += (float)d2 * ts23.x * Hs2;
            An.w += (float)d3 * ts23.y * Hs3;
            float m  = fmaxf(fmaxf(An.x, An.y), fmaxf(An.z, An.w));
            float e0 = __expf(An.x - m), e1 = __expf(An.y - m);
            float e2 = __expf(An.z - m), e3 = __expf(An.w - m);
            float inv = 1.0f / (e0 + e1 + e2 + e3);
            Ap[j] = An;
            float4 nA = make_float4(e0 * inv, e1 * inv, e2 * inv, e3 * inv);
            normAo[j] = nA;
            dval.x += nA.x; dval.y += nA.y; dval.z += nA.z; dval.w += nA.w;
        }
    }
    // reduce dval across warp
    #pragma unroll
    for (int o = 16; o >= 1; o >>= 1) {
        dval.x += __shfl_xor_sync(0xffffffffu, dval.x, o);
        dval.y += __shfl_xor_sync(0xffffffffu, dval.y, o);
        dval.z += __shfl_xor_sync(0xffffffffu, dval.z, o);
        dval.w += __shfl_xor_sync(0xffffffffu, dval.w, o);
    }
    float4 dN = make_float4(rsqrtf(fmaxf(dval.x, 1e-8f)),
                            rsqrtf(fmaxf(dval.y, 1e-8f)),
                            rsqrtf(fmaxf(dval.z, 1e-8f)),
                            rsqrtf(fmaxf(dval.w, 1e-8f)));
    if (lane == 0) dinvN[w] = dN;
    float dNf = (f == 0) ? dN.x : (f == 1) ? dN.y : (f == 2) ? dN.z : dN.w;

    if (mode == 1) {
        // next layer's ego row == acc: write prescaled egoS and max-scaled Tn8/Tsc
        egoSN[w * 32 + lane] = pack_h2(acc.x * dNf, acc.y * dNf);
        float v0 = tanhf(acc.x * hinv), v1 = tanhf(acc.y * hinv);
        float tm = fmaxf(fabsf(v0), fabsf(v1));
        #pragma unroll
        for (int o = 4; o >= 1; o >>= 1) tm = fmaxf(tm, __shfl_xor_sync(0xffffffffu, tm, o));
        tm = fmaxf(tm, 1e-12f);
        float tqs = 127.0f / tm;
        int bx = __float2int_rn(v0 * tqs);
        int by = __float2int_rn(v1 * tqs);
        reinterpret_cast<unsigned short*>(Tn8N)[w * 32 + lane] =
            (unsigned short)((bx & 0xFF) | ((by & 0xFF) << 8));
        if ((lane & 7) == 0) TscN[w * 4 + f] = h_bits(tm * (1.0f / 127.0f));
    } else {
        // same layer: egoS_next = layer ego * dinvN
        float2 src = reinterpret_cast<const float2*>(ego + w * kD)[lane];
        egoSN[w * 32 + lane] = pack_h2(src.x * dNf, src.y * dNf);
    }
}

// ---------------- host driver ----------------
extern "C" void kernel_launch(void* const* d_in, const int* in_sizes, int n_in,
                              void* d_out, int out_size) {
    const float* user = (const float*)d_in[0];
    const float* item = (const float*)d_in[1];
    const int*   hl   = (const int*)d_in[2];
    const int*   tl   = (const int*)d_in[3];
    float* out = (float*)d_out;

    const int TB = 256;
    k_init_ego<<<(kN * kD + TB - 1) / TB, TB>>>(user, item);   // + cnt zeroing
    k_count<<<(kE + TB - 1) / TB, TB>>>(hl);
    k_chunk_reduce<<<kNChunk, TB>>>();                         // + bsum scan (last block)
    k_chunk_scan<<<kNChunk, TB>>>();                           // + dinv0
    k_fill_tail<<<(kE + TB - 1) / TB, TB>>>(hl, tl);           // + Tn8_0/Tsc0/egoS0 prep

    const int FG = kN / 8;   // 8 warps / block
    // L0it0: read egoS0/Tn8_0/dinvA; write dinvB, egoS1 = buf0*dinvB
    k_fused<<<FG, TB>>>(0, 0, 0, 0, 0, out);
    // L0it1: read egoS1/Tn8_0/dinvB; write dinvA, egoS0 = acc*dinvA, Tn8_1/Tsc1; fe->buf1
    k_fused<<<FG, TB>>>(0, 1, 1, 0, 1, out);
    // L1it0: read egoS0/Tn8_1/dinvA; write dinvB, egoS1 = buf1*dinvB
    k_fused<<<FG, TB>>>(1, 0, 0, 1, 0, out);
    // L1it1: final output; read egoS1/dinvB
    k_fused<<<FG, TB>>>(1, 1, 1, 1, 2, out);
    (void)in_sizes; (void)n_in; (void)out_size;
}

// round 17
// speedup vs baseline: 1.1810x; 1.1810x over previous
#include <cuda_runtime.h>
#include <cuda_fp16.h>
#include <cuda_bf16.h>

namespace {
constexpr int kNUser = 50000;
constexpr int kN     = 80000;      // total nodes
constexpr int kE     = 1000000;    // 2 * NNZ symmetric edges
constexpr int kD     = 64;
constexpr int kChunk = 1024;
constexpr int kNChunk = (kN + kChunk - 1) / kChunk;   // 79
}

// ---------------- device scratch (static, no allocation) ----------------
__device__ float    g_A[kE * 4];        // routing logits, CSR-slot order
__device__ float    g_normA[kE * 4];    // softmax(A), CSR-slot order
__device__ float    g_buf0[kN * kD];    // initial ego (layer-0 input; never overwritten)
__device__ float    g_buf1[kN * kD];    // layer-0 output = layer-1 input
__device__ unsigned g_egoS0[kN * 32];   // prescaled ego, fp16 x2, ping (128B/node)
__device__ unsigned g_egoS1[kN * 32];   // pong
__device__ unsigned g_Tn8_0[kN * 16];   // tanh chunks, int8 fixed-scale, ping (64B/node)
__device__ unsigned g_Tn8_1[kN * 16];   // pong
__device__ float    g_dinvA[kN * 4];    // 1/sqrt(degree-weight), ping
__device__ float    g_dinvB[kN * 4];    // pong
__device__ int      g_ptr[kN + 1];      // CSR row pointers (by head)
__device__ int      g_cnt[kN];          // histogram / fill counters
__device__ int      g_csr_t[kE];        // tail node per CSR slot
__device__ int      g_bsum[kNChunk];    // per-chunk sums for multi-block scan
__device__ int      g_red_done;         // last-block-done counter (self-resetting)

__device__ __forceinline__ unsigned pack_h2(float a, float b) {
    __half2 h = __floats2half2_rn(a, b);
    return *reinterpret_cast<unsigned*>(&h);
}
__device__ __forceinline__ int q8(float x) {           // x in [-1,1]
    return __float2int_rn(x * 127.0f);
}
__device__ __forceinline__ unsigned pack_b4(int a, int b, int c, int d) {
    return (unsigned)(a & 0xFF) | ((unsigned)(b & 0xFF) << 8) |
           ((unsigned)(c & 0xFF) << 16) | ((unsigned)(d & 0xFF) << 24);
}

// ---------------- init (+ cnt zeroing folded in) ----------------
__global__ void k_init_ego(const float* __restrict__ user, const float* __restrict__ item) {
    int i = blockIdx.x * blockDim.x + threadIdx.x;
    if (i >= kN * kD) return;
    g_buf0[i] = (i < kNUser * kD) ? user[i] : item[i - kNUser * kD];
    if (i < kN) g_cnt[i] = 0;
}

// ---------------- CSR build ----------------
__global__ void k_count(const int* __restrict__ h) {
    int e = blockIdx.x * blockDim.x + threadIdx.x;
    if (e >= kE) return;
    atomicAdd(&g_cnt[h[e]], 1);
}

// chunk reduce + (last block) scan of the 79 block sums
__global__ void k_chunk_reduce() {            // kNChunk blocks x 256
    __shared__ int wsum[8];
    __shared__ int lastFlag;
    const int lane = threadIdx.x & 31, wrp = threadIdx.x >> 5;
    int base = blockIdx.x * kChunk + (int)threadIdx.x * 4;
    int s = 0;
    #pragma unroll
    for (int k = 0; k < 4; k++) { int i = base + k; if (i < kN) s += g_cnt[i]; }
    #pragma unroll
    for (int o = 16; o >= 1; o >>= 1) s += __shfl_xor_sync(0xffffffffu, s, o);
    if (lane == 0) wsum[wrp] = s;
    __syncthreads();
    if (threadIdx.x == 0) {
        int t = 0;
        #pragma unroll
        for (int k = 0; k < 8; k++) t += wsum[k];
        g_bsum[blockIdx.x] = t;
        __threadfence();
        int v = atomicAdd(&g_red_done, 1);
        lastFlag = (v == (int)gridDim.x - 1) ? 1 : 0;
    }
    __syncthreads();
    if (lastFlag && threadIdx.x < 32) {
        int carry = 0;
        for (int b2 = 0; b2 < kNChunk; b2 += 32) {
            int i = b2 + (int)threadIdx.x;
            int v = (i < kNChunk) ? __ldcg(&g_bsum[i]) : 0;
            int x = v;
            #pragma unroll
            for (int o = 1; o < 32; o <<= 1) {
                int y = __shfl_up_sync(0xffffffffu, x, o);
                if ((int)threadIdx.x >= o) x += y;
            }
            if (i < kNChunk) g_bsum[i] = carry + x - v;   // exclusive
            carry += __shfl_sync(0xffffffffu, x, 31);
        }
        if (threadIdx.x == 0) { g_ptr[kN] = carry; g_red_done = 0; }
    }
}

// chunk scan + dinv0 folded in (degree is in registers here)
__global__ void k_chunk_scan() {              // kNChunk blocks x 256
    __shared__ int wsum[8];
    const int lane = threadIdx.x & 31, wrp = threadIdx.x >> 5;
    int base = blockIdx.x * kChunk + (int)threadIdx.x * 4;
    int v0 = 0, v1 = 0, v2 = 0, v3 = 0;
    if (base + 3 < kN) {
        int4 v = *reinterpret_cast<const int4*>(&g_cnt[base]);
        v0 = v.x; v1 = v.y; v2 = v.z; v3 = v.w;
    } else {
        if (base + 0 < kN) v0 = g_cnt[base + 0];
        if (base + 1 < kN) v1 = g_cnt[base + 1];
        if (base + 2 < kN) v2 = g_cnt[base + 2];
        if (base + 3 < kN) v3 = g_cnt[base + 3];
    }
    int tot = v0 + v1 + v2 + v3;
    int x = tot;
    #pragma unroll
    for (int o = 1; o < 32; o <<= 1) {
        int y = __shfl_up_sync(0xffffffffu, x, o);
        if (lane >= o) x += y;
    }
    if (lane == 31) wsum[wrp] = x;
    __syncthreads();
    if (wrp == 0 && lane < 8) {
        int s = wsum[lane], xs = s;
        #pragma unroll
        for (int o = 1; o < 8; o <<= 1) {
            int y = __shfl_up_sync(0xffu, xs, o);
            if (lane >= o) xs += y;
        }
        wsum[lane] = xs - s;
    }
    __syncthreads();
    int ex = g_bsum[blockIdx.x] + wsum[wrp] + (x - tot);
    int vv[4] = {v0, v1, v2, v3};
    int pre[4] = {0, v0, v0 + v1, v0 + v1 + v2};
    #pragma unroll
    for (int k = 0; k < 4; k++) {
        int n = base + k;
        if (n < kN) {
            g_ptr[n] = ex + pre[k];
            g_cnt[n] = 0;
            float di = rsqrtf(fmaxf(0.25f * (float)vv[k], 1e-8f));
            reinterpret_cast<float4*>(g_dinvA)[n] = make_float4(di, di, di, di);
        }
    }
}

// fill CSR + layer-0 tail prep (Tn8_0 fixed-scale, egoS0). A/normA are NOT
// initialized: the first fused pass uses A=1 / normA=0.25 as constants.
__global__ void k_fill_tail(const int* __restrict__ h, const int* __restrict__ t) {
    int i = blockIdx.x * blockDim.x + threadIdx.x;
    if (i < kE) {
        int hn   = h[i];
        int slot = g_ptr[hn] + atomicAdd(&g_cnt[hn], 1);
        g_csr_t[slot] = t[i];
    }
    if (i < kN * 4) {
        const float4* src = reinterpret_cast<const float4*>(g_buf0) + i * 4;
        float4 v0 = src[0], v1 = src[1], v2 = src[2], v3 = src[3];
        float ss = v0.x*v0.x + v0.y*v0.y + v0.z*v0.z + v0.w*v0.w
                 + v1.x*v1.x + v1.y*v1.y + v1.z*v1.z + v1.w*v1.w
                 + v2.x*v2.x + v2.y*v2.y + v2.z*v2.z + v2.w*v2.w
                 + v3.x*v3.x + v3.y*v3.y + v3.z*v3.z + v3.w*v3.w;
        float inv = 1.0f / fmaxf(sqrtf(ss), 1e-12f);
        uint4 tq;
        tq.x = pack_b4(q8(tanhf(v0.x*inv)), q8(tanhf(v0.y*inv)), q8(tanhf(v0.z*inv)), q8(tanhf(v0.w*inv)));
        tq.y = pack_b4(q8(tanhf(v1.x*inv)), q8(tanhf(v1.y*inv)), q8(tanhf(v1.z*inv)), q8(tanhf(v1.w*inv)));
        tq.z = pack_b4(q8(tanhf(v2.x*inv)), q8(tanhf(v2.y*inv)), q8(tanhf(v2.z*inv)), q8(tanhf(v2.w*inv)));
        tq.w = pack_b4(q8(tanhf(v3.x*inv)), q8(tanhf(v3.y*inv)), q8(tanhf(v3.z*inv)), q8(tanhf(v3.w*inv)));
        reinterpret_cast<uint4*>(g_Tn8_0)[i] = tq;
        float di = g_dinvA[i];
        uint4 s0, s1;
        s0.x = pack_h2(v0.x*di, v0.y*di);
        s0.y = pack_h2(v0.z*di, v0.w*di);
        s0.z = pack_h2(v1.x*di, v1.y*di);
        s0.w = pack_h2(v1.z*di, v1.w*di);
        s1.x = pack_h2(v2.x*di, v2.y*di);
        s1.y = pack_h2(v2.z*di, v2.w*di);
        s1.z = pack_h2(v3.x*di, v3.y*di);
        s1.w = pack_h2(v3.z*di, v3.w*di);
        reinterpret_cast<uint4*>(g_egoS0)[i * 2]     = s0;
        reinterpret_cast<uint4*>(g_egoS0)[i * 2 + 1] = s1;
    }
}

// ---------------- fused iteration ----------------
// one warp per node. MP: fp16 egoS row (128B, 1 line/edge), smem-staged weights.
// Routing: lane-per-edge; Tn row = 64B int8 fixed-scale; head int8 PER-FACTOR
// max-scaled (scales fold into per-node dequant constants -> zero per-edge cost).
// aRd: read A (else base = 1); aWr: write A; nRd: read normA (else 0.25).
// mode: 0 = routing, egoS_next = ego[w]*dinvN
//       1 = routing + fe write, egoS_next = acc*dinvN, Tn8_next = q8(tanh(acc*hinv))
//       2 = final output
__global__ void __launch_bounds__(256) k_fused(
        int sel_in, int dsel, int esel, int tsel, int mode,
        int aRd, int aWr, int nRd, float* __restrict__ out)
{
    __shared__ int            sm_t[8][32];
    __shared__ float          sm_wT[8][4][33];
    __shared__ unsigned short sm_hq[8][32];   // int8x2 quantized head
    __shared__ float          sm_hs[8][4];    // per-factor head dequant constants

    const int warp = threadIdx.x >> 5;
    const int lane = threadIdx.x & 31;
    const int w = blockIdx.x * 8 + warp;
    const int f = lane >> 3;

    const float*    ego    = sel_in ? g_buf1 : g_buf0;
    float*          fe     = sel_in ? g_buf0 : g_buf1;
    const unsigned* egoSC  = esel ? g_egoS1 : g_egoS0;
    unsigned*       egoSN  = esel ? g_egoS0 : g_egoS1;
    const unsigned* Tn8C   = tsel ? g_Tn8_1 : g_Tn8_0;
    unsigned*       Tn8N   = tsel ? g_Tn8_0 : g_Tn8_1;
    const float4*   dinvC  = reinterpret_cast<const float4*>(dsel ? g_dinvB : g_dinvA);
    float4*         dinvN  = reinterpret_cast<float4*>(dsel ? g_dinvA : g_dinvB);
    const float4*   normA  = reinterpret_cast<const float4*>(g_normA);
    float4*         normAo = reinterpret_cast<float4*>(g_normA);
    float4*         Ap     = reinterpret_cast<float4*>(g_A);

    const int s = g_ptr[w], e = g_ptr[w + 1];
    const bool single = (e - s) <= 32;     // sm_t holds ALL tails after MP

    // ---- message passing ----
    float2 acc = make_float2(0.f, 0.f);
    for (int base = s; base < e; base += 32) {
        int j = base + lane;
        bool valid = j < e;
        int t = valid ? g_csr_t[j] : 0;
        float4 na;
        if (valid) {
            na = nRd ? normA[j] : make_float4(.25f, .25f, .25f, .25f);
        } else {
            na = make_float4(0.f, 0.f, 0.f, 0.f);
        }
        sm_t[warp][lane] = t;
        sm_wT[warp][0][lane] = na.x;
        sm_wT[warp][1][lane] = na.y;
        sm_wT[warp][2][lane] = na.z;
        sm_wT[warp][3][lane] = na.w;
        __syncwarp();
        int cnt = min(32, e - base);
        #pragma unroll 8
        for (int k = 0; k < cnt; k++) {
            int   tk = sm_t[warp][k];
            float wk = sm_wT[warp][f][k];
            float2 ev = __half22float2(*reinterpret_cast<const __half2*>(&egoSC[tk * 32 + lane]));
            acc.x += wk * ev.x;
            acc.y += wk * ev.y;
        }
        __syncwarp();
    }
    {
        float4 dh = dinvC[w];
        float ds = (f == 0) ? dh.x : (f == 1) ? dh.y : (f == 2) ? dh.z : dh.w;
        acc.x *= ds; acc.y *= ds;
    }

    if (mode == 2) {
        float2 a = reinterpret_cast<const float2*>(g_buf0 + w * kD)[lane];
        float2 b = reinterpret_cast<const float2*>(ego + w * kD)[lane];
        float2 o;
        o.x = (a.x + b.x + acc.x) * (1.0f / 3.0f);
        o.y = (a.y + b.y + acc.y) * (1.0f / 3.0f);
        reinterpret_cast<float2*>(out + w * kD)[lane] = o;
        return;
    }

    if (mode == 1)
        reinterpret_cast<float2*>(fe + w * kD)[lane] = acc;

    // ---- head inverse norm + per-factor max-scaled int8 quantization ----
    float ss = acc.x * acc.x + acc.y * acc.y;
    #pragma unroll
    for (int o = 4; o >= 1; o >>= 1) ss += __shfl_xor_sync(0xffffffffu, ss, o);
    const float hinv = 1.0f / fmaxf(sqrtf(ss), 1e-12f);
    const float hx = acc.x * hinv, hy = acc.y * hinv;
    float hm = fmaxf(fabsf(hx), fabsf(hy));
    #pragma unroll
    for (int o = 4; o >= 1; o >>= 1) hm = fmaxf(hm, __shfl_xor_sync(0xffffffffu, hm, o));
    hm = fmaxf(hm, 1e-12f);
    {
        float qs = 127.0f / hm;
        int bx = __float2int_rn(hx * qs);
        int by = __float2int_rn(hy * qs);
        sm_hq[warp][lane] = (unsigned short)((bx & 0xFF) | ((by & 0xFF) << 8));
        // dequant constant: d * hm/(127*127)  (Tn fixed 1/127 folded in)
        if ((lane & 7) == 0) sm_hs[warp][f] = hm * (1.0f / (127.0f * 127.0f));
    }
    __syncwarp();
    const float cF0 = sm_hs[warp][0], cF1 = sm_hs[warp][1];
    const float cF2 = sm_hs[warp][2], cF3 = sm_hs[warp][3];

    // ---- routing: lane-per-edge, int8 Tn row (64B) + dp4a, per-lane softmax ----
    const int* hq32 = reinterpret_cast<const int*>(&sm_hq[warp][0]);  // 16 words
    float4 dval = make_float4(0.f, 0.f, 0.f, 0.f);
    for (int base = s; base < e; base += 32) {
        int j = base + lane;
        if (j < e) {
            int t = single ? sm_t[warp][lane] : g_csr_t[j];
            const uint4* tn = reinterpret_cast<const uint4*>(Tn8C) + t * 4;
            int d0, d1, d2, d3;
            {
                uint4 v = tn[0];   // factor 0, dims 0..15
                d0 = __dp4a((int)v.x, hq32[0], 0);
                d0 = __dp4a((int)v.y, hq32[1], d0);
                d0 = __dp4a((int)v.z, hq32[2], d0);
                d0 = __dp4a((int)v.w, hq32[3], d0);
            }
            {
                uint4 v = tn[1];   // factor 1
                d1 = __dp4a((int)v.x, hq32[4], 0);
                d1 = __dp4a((int)v.y, hq32[5], d1);
                d1 = __dp4a((int)v.z, hq32[6], d1);
                d1 = __dp4a((int)v.w, hq32[7], d1);
            }
            {
                uint4 v = tn[2];   // factor 2
                d2 = __dp4a((int)v.x, hq32[8],  0);
                d2 = __dp4a((int)v.y, hq32[9],  d2);
                d2 = __dp4a((int)v.z, hq32[10], d2);
                d2 = __dp4a((int)v.w, hq32[11], d2);
            }
            {
                uint4 v = tn[3];   // factor 3
                d3 = __dp4a((int)v.x, hq32[12], 0);
                d3 = __dp4a((int)v.y, hq32[13], d3);
                d3 = __dp4a((int)v.z, hq32[14], d3);
                d3 = __dp4a((int)v.w, hq32[15], d3);
            }
            float4 An = aRd ? Ap[j] : make_float4(1.f, 1.f, 1.f, 1.f);
            An.x += (float)d0 * cF0;
            An.y += (float)d1 * cF1;
            An.z += (float)d2 * cF2;
            An.w += (float)d3 * cF3;
            float m  = fmaxf(fmaxf(An.x, An.y), fmaxf(An.z, An.w));
            float e0 = __expf(An.x - m), e1 = __expf(An.y - m);
            float e2 = __expf(An.z - m), e3 = __expf(An.w - m);
            float inv = 1.0f / (e0 + e1 + e2 + e3);
            if (aWr) Ap[j] = An;
            float4 nA = make_float4(e0 * inv, e1 * inv, e2 * inv, e3 * inv);
            normAo[j] = nA;
            dval.x += nA.x; dval.y += nA.y; dval.z += nA.z; dval.w += nA.w;
        }
    }
    // reduce dval across warp
    #pragma unroll
    for (int o = 16; o >= 1; o >>= 1) {
        dval.x += __shfl_xor_sync(0xffffffffu, dval.x, o);
        dval.y += __shfl_xor_sync(0xffffffffu, dval.y, o);
        dval.z += __shfl_xor_sync(0xffffffffu, dval.z, o);
        dval.w += __shfl_xor_sync(0xffffffffu, dval.w, o);
    }
    float4 dN = make_float4(rsqrtf(fmaxf(dval.x, 1e-8f)),
                            rsqrtf(fmaxf(dval.y, 1e-8f)),
                            rsqrtf(fmaxf(dval.z, 1e-8f)),
                            rsqrtf(fmaxf(dval.w, 1e-8f)));
    if (lane == 0) dinvN[w] = dN;
    float dNf = (f == 0) ? dN.x : (f == 1) ? dN.y : (f == 2) ? dN.z : dN.w;

    if (mode == 1) {
        // next layer's ego row == acc: write prescaled egoS and fixed-scale Tn8
        egoSN[w * 32 + lane] = pack_h2(acc.x * dNf, acc.y * dNf);
        int bx = q8(tanhf(acc.x * hinv));
        int by = q8(tanhf(acc.y * hinv));
        reinterpret_cast<unsigned short*>(Tn8N)[w * 32 + lane] =
            (unsigned short)((bx & 0xFF) | ((by & 0xFF) << 8));
    } else {
        // same layer: egoS_next = layer ego * dinvN
        float2 src = reinterpret_cast<const float2*>(ego + w * kD)[lane];
        egoSN[w * 32 + lane] = pack_h2(src.x * dNf, src.y * dNf);
    }
}

// ---------------- host driver ----------------
extern "C" void kernel_launch(void* const* d_in, const int* in_sizes, int n_in,
                              void* d_out, int out_size) {
    const float* user = (const float*)d_in[0];
    const float* item = (const float*)d_in[1];
    const int*   hl   = (const int*)d_in[2];
    const int*   tl   = (const int*)d_in[3];
    float* out = (float*)d_out;

    const int TB = 256;
    k_init_ego<<<(kN * kD + TB - 1) / TB, TB>>>(user, item);   // + cnt zeroing
    k_count<<<(kE + TB - 1) / TB, TB>>>(hl);
    k_chunk_reduce<<<kNChunk, TB>>>();                         // + bsum scan (last block)
    k_chunk_scan<<<kNChunk, TB>>>();                           // + dinv0
    k_fill_tail<<<(kE + TB - 1) / TB, TB>>>(hl, tl);           // + Tn8_0/egoS0 prep

    const int FG = kN / 8;   // 8 warps / block
    // L0it0: normA==0.25 const, A==1 const (no loads); write A, dinvB, egoS1
    k_fused<<<FG, TB>>>(0, 0, 0, 0, 0, /*aRd=*/0, /*aWr=*/1, /*nRd=*/0, out);
    // L0it1: read A/normA; write A, dinvA, egoS0 = acc*dinvA, Tn8_1; fe->buf1
    k_fused<<<FG, TB>>>(0, 1, 1, 0, 1, /*aRd=*/1, /*aWr=*/1, /*nRd=*/1, out);
    // L1it0: read A/normA; A store is dead -> skip; write dinvB, egoS1
    k_fused<<<FG, TB>>>(1, 0, 0, 1, 0, /*aRd=*/1, /*aWr=*/0, /*nRd=*/1, out);
    // L1it1: final output; read normA/egoS1/dinvB
    k_fused<<<FG, TB>>>(1, 1, 1, 1, 2, /*aRd=*/0, /*aWr=*/0, /*nRd=*/1, out);
    (void)in_sizes; (void)n_in; (void)out_size;
}